// round 3
// baseline (speedup 1.0000x reference)
#include <cuda_runtime.h>

// Problem constants
#define NG 2048   // G
#define NB 32     // B (batch) -- one warp lane per b
#define NC 16     // C
#define NS 8      // S
#define NM 16     // m
#define FGAMMA 0.01f
#define FINVG  100.0f

#define NBLK 128            // persistent grid: guaranteed resident (<= 1 block/SM)
#define NTHR 256            // 8 warps / block
#define NWARPS (NBLK * NTHR / 32)   // 1024 persistent warps
#define NTOT  (NBLK * NTHR)         // 32768 threads

// Scratch (device globals -- no allocation allowed)
__device__ float g_Rt[NG * NB];          // R transposed: Rt[g*32 + b]  (UN-normalized)
__device__ float g_Cv[NC * NG * NB];     // Cv_pre[(c*G+g)*32 + b]
__device__ float g_Hs[NG * NB];          // Hs_pre[g*32 + b]
__device__ float g_Ws[NM * NC];          // softmax(W) rows
__device__ int   g_max[16][8];           // banked float-bit maxes (values >= 0)
// slot 3i=Cv max, 3i+1=Hs max, 3i+2=R max (iter i); slot 15 = constant 1.0

__device__ int            g_bar_count;
__device__ volatile int   g_bar_gen;

// ---------------------------------------------------------------------------
__device__ __forceinline__ float get_scale(int slot) {
    int v = g_max[slot][0];
    #pragma unroll
    for (int k = 1; k < 8; k++) v = max(v, g_max[slot][k]);
    float m = __int_as_float(v);
    return (m > 1.0f) ? __fdividef(1.0f, m) : 1.0f;
}

// warp->block max reduce, one atomicMax per block. All 256 threads must call.
__device__ __forceinline__ void block_max_atomic(float val, int slot) {
    int v = __float_as_int(val);   // valid ordering: all values non-negative
    #pragma unroll
    for (int o = 16; o > 0; o >>= 1) v = max(v, __shfl_xor_sync(0xffffffffu, v, o));
    __shared__ int s_red[8];
    if ((threadIdx.x & 31) == 0) s_red[threadIdx.x >> 5] = v;
    __syncthreads();
    if (threadIdx.x == 0) {
        int m = s_red[0];
        #pragma unroll
        for (int k = 1; k < 8; k++) m = max(m, s_red[k]);
        atomicMax(&g_max[slot][blockIdx.x & 7], m);
    }
}

// software grid barrier (all NBLK blocks resident by construction)
__device__ __forceinline__ void grid_sync() {
    __syncthreads();
    if (threadIdx.x == 0) {
        int gen = g_bar_gen;
        __threadfence();
        if (atomicAdd(&g_bar_count, 1) == NBLK - 1) {
            g_bar_count = 0;
            __threadfence();
            g_bar_gen = gen + 1;
        } else {
            while (g_bar_gen == gen) { }
        }
        __threadfence();
    }
    __syncthreads();
}

// ---------------------------------------------------------------------------
// Init: transpose x -> Rt, Ws = softmax(W, axis=1), reset max banks + barrier.
__global__ void k_init(const float* __restrict__ x, const float* __restrict__ W) {
    int t = blockIdx.x * blockDim.x + threadIdx.x;
    int b = t >> 11;           // t = b*G + g
    int g = t & (NG - 1);
    g_Rt[g * NB + b] = x[t];

    if (blockIdx.x == 0) {
        if (threadIdx.x < NM) {
            int m = threadIdx.x;
            float mx = -1e30f;
            #pragma unroll
            for (int c = 0; c < NC; c++) mx = fmaxf(mx, W[m * NC + c]);
            float e[NC]; float sum = 0.0f;
            #pragma unroll
            for (int c = 0; c < NC; c++) { e[c] = __expf(W[m * NC + c] - mx); sum += e[c]; }
            float inv = __fdividef(1.0f, sum);
            #pragma unroll
            for (int c = 0; c < NC; c++) g_Ws[m * NC + c] = e[c] * inv;
        }
        if (threadIdx.x >= 64 && threadIdx.x < 192) {
            int k = threadIdx.x - 64;
            ((int*)g_max)[k] = (k >= 15 * 8) ? __float_as_int(1.0f) : 0;  // slot 15 == 1.0
        }
        if (threadIdx.x == 255) { g_bar_count = 0; g_bar_gen = 0; }
    }
}

// ---------------------------------------------------------------------------
// Persistent kernel: 5 x (K1 gather/prod/LSE -> K2 matvec/LSE -> K3 merge),
// grid barriers at the 3 global-max sync points per iteration, then output.
__global__ void __launch_bounds__(NTHR, 1)
k_persist(const int* __restrict__ I, float* __restrict__ out) {
    __shared__ float ws[NM * NC];
    ws[threadIdx.x] = g_Ws[threadIdx.x];   // NTHR == 256 == NM*NC
    __syncthreads();

    const int tid   = threadIdx.x;
    const int lane  = tid & 31;
    const int gwarp = blockIdx.x * (NTHR / 32) + (tid >> 5);
    const int gtid  = blockIdx.x * NTHR + tid;

    int slotR = 15;   // iteration 0 uses x unscaled

    #pragma unroll 1
    for (int it = 0; it < 5; it++) {
        const int slotCv = 3 * it, slotHs = 3 * it + 1, slotRn = 3 * it + 2;

        // ---- K1: per (c,g) item, lane = b ----
        {
            float sR = get_scale(slotR);
            float s3 = sR * sR * sR;
            float lmax = 0.0f;
            #pragma unroll 1
            for (int item = gwarp; item < NC * NG; item += NWARPS) {
                const int4* ip = reinterpret_cast<const int4*>(I) + item * 6;
                int4 a0 = ip[0], a1 = ip[1], a2 = ip[2],
                     a3 = ip[3], a4 = ip[4], a5 = ip[5];
                int idx[24] = { a0.x,a0.y,a0.z,a0.w, a1.x,a1.y,a1.z,a1.w,
                                a2.x,a2.y,a2.z,a2.w, a3.x,a3.y,a3.z,a3.w,
                                a4.x,a4.y,a4.z,a4.w, a5.x,a5.y,a5.z,a5.w };
                float body[NS];
                #pragma unroll
                for (int s = 0; s < NS; s++) {
                    float v0 = g_Rt[idx[3 * s + 0] * NB + lane];
                    float v1 = g_Rt[idx[3 * s + 1] * NB + lane];
                    float v2 = g_Rt[idx[3 * s + 2] * NB + lane];
                    body[s] = v0 * v1 * v2 * s3;
                }
                float mx = body[0];
                #pragma unroll
                for (int s = 1; s < NS; s++) mx = fmaxf(mx, body[s]);
                float sum = 0.0f;
                #pragma unroll
                for (int s = 0; s < NS; s++) sum += __expf((body[s] - mx) * FINVG);
                float cv = fmaf(FGAMMA, __logf(sum), mx);
                g_Cv[item * NB + lane] = cv;
                lmax = fmaxf(lmax, cv);
            }
            block_max_atomic(lmax, slotCv);
        }
        grid_sync();

        // ---- K2: per g item, lane = b ----
        {
            float s1 = get_scale(slotCv);
            float lmax = 0.0f;
            #pragma unroll 1
            for (int g = gwarp; g < NG; g += NWARPS) {
                float cv[NC];
                #pragma unroll
                for (int c = 0; c < NC; c++)
                    cv[c] = g_Cv[(c * NG + g) * NB + lane] * s1;
                float h[NM];
                #pragma unroll
                for (int m = 0; m < NM; m++) {
                    float acc = 0.0f;
                    #pragma unroll
                    for (int c = 0; c < NC; c++) acc = fmaf(ws[m * NC + c], cv[c], acc);
                    h[m] = acc;
                }
                float mx = h[0];
                #pragma unroll
                for (int m = 1; m < NM; m++) mx = fmaxf(mx, h[m]);
                float sum = 0.0f;
                #pragma unroll
                for (int m = 0; m < NM; m++) sum += __expf((h[m] - mx) * FINVG);
                float hs = fmaf(FGAMMA, __logf(sum), mx);
                g_Hs[g * NB + lane] = hs;
                lmax = fmaxf(lmax, hs);
            }
            block_max_atomic(lmax, slotHs);
        }
        grid_sync();

        // ---- K3: elementwise 2-way softor merge, R updated in place ----
        {
            float sR = get_scale(slotR);
            float s2 = get_scale(slotHs);
            float lmax = 0.0f;
            #pragma unroll
            for (int t = gtid; t < NG * NB; t += NTOT) {
                float a  = g_Rt[t] * sR;
                float hv = g_Hs[t] * s2;
                float mx = fmaxf(a, hv);
                float mn = fminf(a, hv);
                float r  = fmaf(FGAMMA, __logf(1.0f + __expf((mn - mx) * FINVG)), mx);
                g_Rt[t] = r;
                lmax = fmaxf(lmax, r);
            }
            block_max_atomic(lmax, slotRn);
        }
        grid_sync();

        slotR = slotRn;
    }

    // ---- output: scale + transpose back to (B, G) ----
    {
        float s = get_scale(slotR);
        #pragma unroll
        for (int t = gtid; t < NG * NB; t += NTOT) {
            int b = t >> 11;
            int g = t & (NG - 1);
            out[t] = g_Rt[g * NB + b] * s;
        }
    }
}

// ---------------------------------------------------------------------------
extern "C" void kernel_launch(void* const* d_in, const int* in_sizes, int n_in,
                              void* d_out, int out_size) {
    const float* x = (const float*)d_in[0];   // (32, 2048) f32
    const float* W = (const float*)d_in[1];   // (16, 16) f32
    const int*   I = (const int*)  d_in[2];   // (16, 2048, 8, 3) i32
    float* out = (float*)d_out;               // (32, 2048) f32

    k_init<<<256, 256>>>(x, W);
    k_persist<<<NBLK, NTHR>>>(I, out);
}

// round 4
// speedup vs baseline: 1.4131x; 1.4131x over previous
#include <cuda_runtime.h>

// Problem constants
#define NG 2048   // G
#define NB 32     // B -- one warp lane per b
#define NC 16     // C
#define NS 8      // S
#define NM 16     // m
#define FGAMMA 0.01f
#define FINVG  100.0f

#define NBLK 256            // 2 blocks/SM capacity (launch_bounds(256,2)) -> all resident
#define NTHR 256            // 8 warps/block
#define NWARPS (NBLK * NTHR / 32)   // 2048 warps == NG (one g per warp)
#define NTOT  (NBLK * NTHR)         // 65536 == NG*NB

// Scratch (device globals -- no allocation allowed)
__device__ float g_Rt[NG * NB];          // R transposed: Rt[g*32 + b] (UN-normalized)
__device__ float g_Ws[NM * NC];          // softmax(W) rows
__device__ int   g_max[16][8];           // banked float-bit maxes (values >= 0)
// slot 3i=Cv max, 3i+1=Hs max, 3i+2=R max (iter i); slot 15 = constant 1.0

__device__ int          g_bar_count;     // zero at load; self-resetting
__device__ volatile int g_bar_gen;       // monotonically increments across replays

// ---------------------------------------------------------------------------
__device__ __forceinline__ float get_scale(int slot) {
    int v = g_max[slot][0];
    #pragma unroll
    for (int k = 1; k < 8; k++) v = max(v, g_max[slot][k]);
    float m = __int_as_float(v);
    return (m > 1.0f) ? __fdividef(1.0f, m) : 1.0f;
}

// warp->block max reduce, one atomicMax per block. All 256 threads must call.
__device__ __forceinline__ void block_max_atomic(float val, int slot) {
    int v = __float_as_int(val);   // valid ordering: all values non-negative
    #pragma unroll
    for (int o = 16; o > 0; o >>= 1) v = max(v, __shfl_xor_sync(0xffffffffu, v, o));
    __shared__ int s_red[8];
    if ((threadIdx.x & 31) == 0) s_red[threadIdx.x >> 5] = v;
    __syncthreads();
    if (threadIdx.x == 0) {
        int m = s_red[0];
        #pragma unroll
        for (int k = 1; k < 8; k++) m = max(m, s_red[k]);
        atomicMax(&g_max[slot][blockIdx.x & 7], m);
    }
}

// software grid barrier; all NBLK blocks resident by construction
__device__ __forceinline__ void grid_sync() {
    __syncthreads();
    if (threadIdx.x == 0) {
        int gen = g_bar_gen;
        __threadfence();
        if (atomicAdd(&g_bar_count, 1) == NBLK - 1) {
            g_bar_count = 0;
            __threadfence();
            g_bar_gen = gen + 1;
        } else {
            while (g_bar_gen == gen) { }
        }
        __threadfence();
    }
    __syncthreads();
}

// ---------------------------------------------------------------------------
// Single persistent kernel: init + 5 x (fused K1K2 -> Hs -> merge) + output.
__global__ void __launch_bounds__(NTHR, 2)
k_persist(const float* __restrict__ x, const float* __restrict__ W,
          const int* __restrict__ I, float* __restrict__ out) {
    const int tid   = threadIdx.x;
    const int lane  = tid & 31;                       // b
    const int g     = blockIdx.x * 8 + (tid >> 5);    // 2048 warps == 2048 g's
    const int gtid  = blockIdx.x * NTHR + tid;

    // ---- init phase (replaces k_init launch) ----
    {
        int b = gtid >> 11, gg = gtid & (NG - 1);     // gtid covers 32*2048 exactly
        g_Rt[gg * NB + b] = x[gtid];
        if (blockIdx.x == 0 && tid < NM) {            // Ws = softmax(W) row tid
            float mx = -1e30f;
            #pragma unroll
            for (int c = 0; c < NC; c++) mx = fmaxf(mx, W[tid * NC + c]);
            float e[NC]; float sum = 0.0f;
            #pragma unroll
            for (int c = 0; c < NC; c++) { e[c] = __expf(W[tid * NC + c] - mx); sum += e[c]; }
            float inv = __fdividef(1.0f, sum);
            #pragma unroll
            for (int c = 0; c < NC; c++) g_Ws[tid * NC + c] = e[c] * inv;
        }
        if (blockIdx.x == 1 && tid < 128)             // reset 16 slots x 8 banks
            ((int*)g_max)[tid] = (tid >= 15 * 8) ? __float_as_int(1.0f) : 0;
    }
    grid_sync();

    __shared__ float ws[NM * NC];
    ws[tid] = g_Ws[tid];
    __syncthreads();

    int slotR = 15;   // iteration 0 uses x unscaled (slot 15 == 1.0)

    #pragma unroll 1
    for (int it = 0; it < 5; it++) {
        const int slotCv = 3 * it, slotHs = 3 * it + 1, slotRn = 3 * it + 2;

        // ---- Phase A: fused K1 + K2-matvec. h[m] accumulated in registers ----
        float h[NM];
        #pragma unroll
        for (int m = 0; m < NM; m++) h[m] = 0.0f;
        {
            float sR = get_scale(slotR);
            float s3 = sR * sR * sR;
            float lmax = 0.0f;
            const int4* ipg = reinterpret_cast<const int4*>(I) + g * 6;

            #pragma unroll 1
            for (int c = 0; c < NC; c++) {
                const int4* ip = ipg + c * (NG * 6);
                int4 a0 = ip[0], a1 = ip[1], a2 = ip[2],
                     a3 = ip[3], a4 = ip[4], a5 = ip[5];
                int idx[24] = { a0.x,a0.y,a0.z,a0.w, a1.x,a1.y,a1.z,a1.w,
                                a2.x,a2.y,a2.z,a2.w, a3.x,a3.y,a3.z,a3.w,
                                a4.x,a4.y,a4.z,a4.w, a5.x,a5.y,a5.z,a5.w };
                float body[NS];
                #pragma unroll
                for (int s = 0; s < NS; s++) {
                    float v0 = g_Rt[idx[3 * s + 0] * NB + lane];
                    float v1 = g_Rt[idx[3 * s + 1] * NB + lane];
                    float v2 = g_Rt[idx[3 * s + 2] * NB + lane];
                    body[s] = v0 * v1 * v2 * s3;
                }
                float mx = body[0];
                #pragma unroll
                for (int s = 1; s < NS; s++) mx = fmaxf(mx, body[s]);
                float sum = 0.0f;
                #pragma unroll
                for (int s = 0; s < NS; s++) sum += __expf((body[s] - mx) * FINVG);
                float cv = fmaf(FGAMMA, __logf(sum), mx);
                lmax = fmaxf(lmax, cv);
                #pragma unroll
                for (int m = 0; m < NM; m++) h[m] = fmaf(ws[m * NC + c], cv, h[m]);
            }
            block_max_atomic(lmax, slotCv);
        }
        grid_sync();

        // ---- Phase B: Hs = gamma*LSE_m(s1*h[m]/gamma); kept in register ----
        float hs;
        {
            float s1 = get_scale(slotCv);
            float mx = h[0];
            #pragma unroll
            for (int m = 1; m < NM; m++) mx = fmaxf(mx, h[m]);
            mx *= s1;   // s1 > 0
            float sum = 0.0f;
            #pragma unroll
            for (int m = 0; m < NM; m++) sum += __expf((s1 * h[m] - mx) * FINVG);
            hs = fmaf(FGAMMA, __logf(sum), mx);
            block_max_atomic(hs, slotHs);
        }
        grid_sync();

        // ---- Phase C: 2-way softor merge of {R_old, Hs}; R updated in place ----
        {
            float sR = get_scale(slotR);
            float s2 = get_scale(slotHs);
            float a  = g_Rt[g * NB + lane] * sR;
            float hv = hs * s2;
            float mx = fmaxf(a, hv);
            float mn = fminf(a, hv);
            float r  = fmaf(FGAMMA, __logf(1.0f + __expf((mn - mx) * FINVG)), mx);
            g_Rt[g * NB + lane] = r;
            block_max_atomic(r, slotRn);
        }
        grid_sync();

        slotR = slotRn;
    }

    // ---- output: scale + transpose back to (B, G); coalesced store ----
    {
        float s = get_scale(slotR);
        int b = gtid >> 11, gg = gtid & (NG - 1);
        out[gtid] = g_Rt[gg * NB + b] * s;
    }
}

// ---------------------------------------------------------------------------
extern "C" void kernel_launch(void* const* d_in, const int* in_sizes, int n_in,
                              void* d_out, int out_size) {
    const float* x = (const float*)d_in[0];   // (32, 2048) f32
    const float* W = (const float*)d_in[1];   // (16, 16) f32
    const int*   I = (const int*)  d_in[2];   // (16, 2048, 8, 3) i32
    float* out = (float*)d_out;               // (32, 2048) f32

    k_persist<<<NBLK, NTHR>>>(x, W, I, out);
}

// round 5
// speedup vs baseline: 1.4152x; 1.0015x over previous
#include <cuda_runtime.h>

// Problem constants
#define NG 2048   // G
#define NB 32     // B -- one warp lane per b
#define NC 16     // C
#define NS 8      // S
#define NM 16     // m
#define FGAMMA 0.01f
#define FINVG  100.0f

#define NBLK 432                    // <= 148 SMs * 3 blocks/SM (launch_bounds(256,3))
#define NTHR 256                    // 8 warps/block
#define NWARP (NBLK * 8)            // 3456 warps
#define NTOT  (NBLK * NTHR)         // 110592 threads
#define NELEM (NG * NB)             // 65536

// Scratch (device globals -- no allocation allowed)
__device__ float g_Rt[NG * NB];          // R transposed: Rt[g*32 + b] (UN-normalized)
__device__ float g_Cv[NC * NG * NB];     // Cv_pre[(c*G+g)*32 + b]
__device__ float g_Hs[NG * NB];          // Hs_pre[g*32 + b]
__device__ float g_Ws[NM * NC];          // softmax(W) rows
__device__ int   g_max[16][8];           // banked float-bit maxes (values >= 0)
// slot 3i=Cv max, 3i+1=Hs max, 3i+2=R max (iter i); slot 15 = constant 1.0

__device__ int          g_bar_count;     // zero at load; self-resetting
__device__ volatile int g_bar_gen;       // monotonically increments across replays

// ---------------------------------------------------------------------------
__device__ __forceinline__ float get_scale(int slot) {
    int v = g_max[slot][0];
    #pragma unroll
    for (int k = 1; k < 8; k++) v = max(v, g_max[slot][k]);
    float m = __int_as_float(v);
    return (m > 1.0f) ? __fdividef(1.0f, m) : 1.0f;
}

// warp->block max reduce, one atomicMax per block. All 256 threads must call.
__device__ __forceinline__ void block_max_atomic(float val, int slot) {
    int v = __float_as_int(val);   // valid ordering: all values non-negative
    #pragma unroll
    for (int o = 16; o > 0; o >>= 1) v = max(v, __shfl_xor_sync(0xffffffffu, v, o));
    __shared__ int s_red[8];
    if ((threadIdx.x & 31) == 0) s_red[threadIdx.x >> 5] = v;
    __syncthreads();
    if (threadIdx.x == 0) {
        int m = s_red[0];
        #pragma unroll
        for (int k = 1; k < 8; k++) m = max(m, s_red[k]);
        atomicMax(&g_max[slot][blockIdx.x & 7], m);
    }
}

// software grid barrier; all NBLK blocks resident by construction
__device__ __forceinline__ void grid_sync() {
    __syncthreads();
    if (threadIdx.x == 0) {
        int gen = g_bar_gen;
        __threadfence();
        if (atomicAdd(&g_bar_count, 1) == NBLK - 1) {
            g_bar_count = 0;
            __threadfence();
            g_bar_gen = gen + 1;
        } else {
            while (g_bar_gen == gen) { __nanosleep(64); }
        }
        __threadfence();
    }
    __syncthreads();
}

// ---------------------------------------------------------------------------
// Single persistent kernel: init + 5 x (A: gather/LSE -> B: matvec/LSE ->
// C: merge) with grid barriers at the 3 global-max sync points, then output.
__global__ void __launch_bounds__(NTHR, 3)
k_persist(const float* __restrict__ x, const float* __restrict__ W,
          const int* __restrict__ I, float* __restrict__ out) {
    const int tid  = threadIdx.x;
    const int lane = tid & 31;                        // b
    const int wid  = blockIdx.x * 8 + (tid >> 5);     // 0..NWARP-1
    const int gtid = blockIdx.x * NTHR + tid;

    // ---- init: transpose x -> Rt, Ws = softmax(W), reset max banks ----
    {
        if (gtid < NELEM) {
            int b = gtid >> 11, gg = gtid & (NG - 1);
            g_Rt[gg * NB + b] = x[gtid];
        }
        if (blockIdx.x == 0 && tid < NM) {
            float mx = -1e30f;
            #pragma unroll
            for (int c = 0; c < NC; c++) mx = fmaxf(mx, W[tid * NC + c]);
            float e[NC]; float sum = 0.0f;
            #pragma unroll
            for (int c = 0; c < NC; c++) { e[c] = __expf(W[tid * NC + c] - mx); sum += e[c]; }
            float inv = __fdividef(1.0f, sum);
            #pragma unroll
            for (int c = 0; c < NC; c++) g_Ws[tid * NC + c] = e[c] * inv;
        }
        if (blockIdx.x == 1 && tid < 128)
            ((int*)g_max)[tid] = (tid >= 15 * 8) ? __float_as_int(1.0f) : 0;
    }
    grid_sync();

    __shared__ float ws[NM * NC];
    ws[tid] = g_Ws[tid];       // NTHR == 256 == NM*NC
    __syncthreads();

    int slotR = 15;   // iteration 0 uses x unscaled (slot 15 == 1.0)

    #pragma unroll 1
    for (int it = 0; it < 5; it++) {
        const int slotCv = 3 * it, slotHs = 3 * it + 1, slotRn = 3 * it + 2;

        // ---- Phase A: per (c,g) item, lane = b; grid-stride, 95% balanced ----
        {
            float sR = get_scale(slotR);
            float s3 = sR * sR * sR;
            float lmax = 0.0f;
            #pragma unroll 1
            for (int item = wid; item < NC * NG; item += NWARP) {
                const int4* ip = reinterpret_cast<const int4*>(I) + item * 6;
                int4 a0 = ip[0], a1 = ip[1], a2 = ip[2],
                     a3 = ip[3], a4 = ip[4], a5 = ip[5];
                int idx[24] = { a0.x,a0.y,a0.z,a0.w, a1.x,a1.y,a1.z,a1.w,
                                a2.x,a2.y,a2.z,a2.w, a3.x,a3.y,a3.z,a3.w,
                                a4.x,a4.y,a4.z,a4.w, a5.x,a5.y,a5.z,a5.w };
                float body[NS];
                #pragma unroll
                for (int s = 0; s < NS; s++) {
                    float v0 = g_Rt[idx[3 * s + 0] * NB + lane];
                    float v1 = g_Rt[idx[3 * s + 1] * NB + lane];
                    float v2 = g_Rt[idx[3 * s + 2] * NB + lane];
                    body[s] = v0 * v1 * v2 * s3;
                }
                float mx = body[0];
                #pragma unroll
                for (int s = 1; s < NS; s++) mx = fmaxf(mx, body[s]);
                float sum = 0.0f;
                #pragma unroll
                for (int s = 0; s < NS; s++) sum += __expf((body[s] - mx) * FINVG);
                float cv = fmaf(FGAMMA, __logf(sum), mx);
                g_Cv[item * NB + lane] = cv;
                lmax = fmaxf(lmax, cv);
            }
            block_max_atomic(lmax, slotCv);
        }
        grid_sync();

        // ---- Phase B: per g, matvec over c (ws in smem) + LSE over m ----
        {
            float s1 = get_scale(slotCv);
            float lmax = 0.0f;
            if (wid < NG) {
                int g = wid;
                float cv[NC];
                #pragma unroll
                for (int c = 0; c < NC; c++)
                    cv[c] = g_Cv[(c * NG + g) * NB + lane] * s1;
                float h[NM];
                #pragma unroll
                for (int m = 0; m < NM; m++) {
                    float acc = 0.0f;
                    #pragma unroll
                    for (int c = 0; c < NC; c++) acc = fmaf(ws[m * NC + c], cv[c], acc);
                    h[m] = acc;
                }
                float mx = h[0];
                #pragma unroll
                for (int m = 1; m < NM; m++) mx = fmaxf(mx, h[m]);
                float sum = 0.0f;
                #pragma unroll
                for (int m = 0; m < NM; m++) sum += __expf((h[m] - mx) * FINVG);
                float hs = fmaf(FGAMMA, __logf(sum), mx);
                g_Hs[g * NB + lane] = hs;
                lmax = hs;
            }
            block_max_atomic(lmax, slotHs);
        }
        grid_sync();

        // ---- Phase C: elementwise 2-way softor merge, R in place ----
        {
            float sR = get_scale(slotR);
            float s2 = get_scale(slotHs);
            float lmax = 0.0f;
            if (gtid < NELEM) {
                float a  = g_Rt[gtid] * sR;
                float hv = g_Hs[gtid] * s2;
                float mx = fmaxf(a, hv);
                float mn = fminf(a, hv);
                float r  = fmaf(FGAMMA, __logf(1.0f + __expf((mn - mx) * FINVG)), mx);
                g_Rt[gtid] = r;
                lmax = r;
            }
            block_max_atomic(lmax, slotRn);
        }
        grid_sync();

        slotR = slotRn;
    }

    // ---- output: scale + transpose back to (B, G); coalesced store ----
    if (gtid < NELEM) {
        float s = get_scale(slotR);
        int b = gtid >> 11, gg = gtid & (NG - 1);
        out[gtid] = g_Rt[gg * NB + b] * s;
    }
}

// ---------------------------------------------------------------------------
extern "C" void kernel_launch(void* const* d_in, const int* in_sizes, int n_in,
                              void* d_out, int out_size) {
    const float* x = (const float*)d_in[0];   // (32, 2048) f32
    const float* W = (const float*)d_in[1];   // (16, 16) f32
    const int*   I = (const int*)  d_in[2];   // (16, 2048, 8, 3) i32
    float* out = (float*)d_out;               // (32, 2048) f32

    k_persist<<<NBLK, NTHR>>>(x, W, I, out);
}

// round 6
// speedup vs baseline: 1.5367x; 1.0858x over previous
#include <cuda_runtime.h>

// Problem constants
#define NG 2048   // G
#define NC 16     // C
#define NM 16     // m
// exp(x/gamma) = ex2(x * 100 * log2(e));  gamma*ln(s) = lg2(s) * gamma*ln2
#define KEXP 144.2695040889f
#define KLOG 0.00693147180560f

#define NBLK 592                 // 148 SMs * 4 blocks; launch_bounds(256,4) -> <=64 regs
#define NTHR 256
#define NW   (NBLK * 8)          // 4736 warps
#define NTOT (NBLK * NTHR)
#define NPAIR (NC * NG / 2)      // 16384 item-pairs in Phase A
#define NEL2  (NG * 16)          // 32768 packed Rt elements

typedef unsigned long long u64;

// Packed layouts: element [g*16+j] = (val[b=2j], val[b=2j+1])
__device__ u64   g_Rt2[NG * 16];         // R (un-normalized; scale in g_max)
__device__ u64   g_Cv2[NC * NG * 16];    // Cv_pre
__device__ float g_Ws[NM * NC];          // softmax(W)
__device__ int   g_max[16][8];           // banked float-bit maxes (values >= 0)
// slot 3i=Cv max, 3i+1=Hs max, 3i+2=R max (iter i); slot 15 = constant 1.0
__device__ int          g_bar_count;
__device__ volatile int g_bar_gen;

// ---- f32x2 helpers (sm_103a packed fp32) ----
__device__ __forceinline__ u64 pk(float x, float y) {
    u64 v; asm("mov.b64 %0, {%1,%2};" : "=l"(v) : "f"(x), "f"(y)); return v;
}
__device__ __forceinline__ float2 unpk(u64 v) {
    float2 r; asm("mov.b64 {%0,%1}, %2;" : "=f"(r.x), "=f"(r.y) : "l"(v)); return r;
}
__device__ __forceinline__ u64 mul2(u64 a, u64 b) {
    u64 c; asm("mul.rn.f32x2 %0, %1, %2;" : "=l"(c) : "l"(a), "l"(b)); return c;
}
__device__ __forceinline__ u64 fma2(u64 a, u64 b, u64 c) {
    u64 d; asm("fma.rn.f32x2 %0, %1, %2, %3;" : "=l"(d) : "l"(a), "l"(b), "l"(c)); return d;
}
__device__ __forceinline__ float ex2(float x) {
    float y; asm("ex2.approx.ftz.f32 %0, %1;" : "=f"(y) : "f"(x)); return y;
}
__device__ __forceinline__ float lg2(float x) {
    float y; asm("lg2.approx.f32 %0, %1;" : "=f"(y) : "f"(x)); return y;
}

// ---------------------------------------------------------------------------
__device__ __forceinline__ float get_scale(int slot) {
    int v = g_max[slot][0];
    #pragma unroll
    for (int k = 1; k < 8; k++) v = max(v, g_max[slot][k]);
    float m = __int_as_float(v);
    return (m > 1.0f) ? __fdividef(1.0f, m) : 1.0f;
}

__device__ __forceinline__ void block_max_atomic(float val, int slot) {
    int v = __float_as_int(val);   // valid ordering: all values non-negative
    #pragma unroll
    for (int o = 16; o > 0; o >>= 1) v = max(v, __shfl_xor_sync(0xffffffffu, v, o));
    __shared__ int s_red[8];
    if ((threadIdx.x & 31) == 0) s_red[threadIdx.x >> 5] = v;
    __syncthreads();
    if (threadIdx.x == 0) {
        int m = s_red[0];
        #pragma unroll
        for (int k = 1; k < 8; k++) m = max(m, s_red[k]);
        atomicMax(&g_max[slot][blockIdx.x & 7], m);
    }
}

// tight-spin grid barrier; all NBLK blocks resident by construction
__device__ __forceinline__ void grid_sync() {
    __syncthreads();
    if (threadIdx.x == 0) {
        int gen = g_bar_gen;
        __threadfence();
        if (atomicAdd(&g_bar_count, 1) == NBLK - 1) {
            g_bar_count = 0;
            __threadfence();
            g_bar_gen = gen + 1;
        } else {
            while (g_bar_gen == gen) { }
        }
        __threadfence();
    }
    __syncthreads();
}

// ---------------------------------------------------------------------------
__global__ void __launch_bounds__(NTHR, 4)
k_persist(const float* __restrict__ x, const float* __restrict__ W,
          const int* __restrict__ I, float* __restrict__ out) {
    const int tid  = threadIdx.x;
    const int lane = tid & 31;
    const int hf   = lane >> 4;                   // which item of the pair
    const int j    = lane & 15;                   // b-pair index
    const int wid  = blockIdx.x * 8 + (tid >> 5); // 0..NW-1
    const int gtid = blockIdx.x * NTHR + tid;

    // ---- init: pack x -> Rt2, Ws = softmax(W), reset max banks ----
    {
        if (gtid < NG * 16) {                     // gtid = jj*NG + g
            int jj = gtid >> 11, g = gtid & (NG - 1);
            g_Rt2[g * 16 + jj] = pk(x[(2 * jj) * NG + g], x[(2 * jj + 1) * NG + g]);
        }
        if (blockIdx.x == 0 && tid < NM) {
            float mx = -1e30f;
            #pragma unroll
            for (int c = 0; c < NC; c++) mx = fmaxf(mx, W[tid * NC + c]);
            float e[NC]; float sum = 0.0f;
            #pragma unroll
            for (int c = 0; c < NC; c++) { e[c] = ex2((W[tid * NC + c] - mx) * 1.4426950409f); sum += e[c]; }
            float inv = __fdividef(1.0f, sum);
            #pragma unroll
            for (int c = 0; c < NC; c++) g_Ws[tid * NC + c] = e[c] * inv;
        }
        if (blockIdx.x == 1 && tid < 128)
            ((int*)g_max)[tid] = (tid >= 15 * 8) ? __float_as_int(1.0f) : 0;
    }
    grid_sync();

    __shared__ u64 ws2[NM * NC];                  // broadcast-packed softmax(W)
    { float w = g_Ws[tid]; ws2[tid] = pk(w, w); }
    __syncthreads();

    int slotR = 15;   // iteration 0 uses x unscaled (slot 15 == 1.0)

    #pragma unroll 1
    for (int it = 0; it < 5; it++) {
        const int slotCv = 3 * it, slotHs = 3 * it + 1, slotRn = 3 * it + 2;

        // ---- Phase A: pair of (c,g) items per warp; f32x2 throughout ----
        {
            float sR = get_scale(slotR);
            float s3 = sR * sR * sR;
            float kexp = s3 * KEXP;               // scale folded into LSE constant
            u64  kexp2 = pk(kexp, kexp);
            float lmax = 0.0f;
            int p0 = (int)(((long long)wid * NPAIR) / NW);
            int p1 = (int)(((long long)(wid + 1) * NPAIR) / NW);
            #pragma unroll 1
            for (int P = p0; P < p1; P++) {
                int item = 2 * P + hf;
                const int4* ip = reinterpret_cast<const int4*>(I) + item * 6;
                int4 a0 = ip[0], a1 = ip[1], a2 = ip[2],
                     a3 = ip[3], a4 = ip[4], a5 = ip[5];
                #define GA(i) g_Rt2[(i) * 16 + j]
                u64 b0 = mul2(mul2(GA(a0.x), GA(a0.y)), GA(a0.z));
                u64 b1 = mul2(mul2(GA(a0.w), GA(a1.x)), GA(a1.y));
                u64 b2 = mul2(mul2(GA(a1.z), GA(a1.w)), GA(a2.x));
                u64 b3 = mul2(mul2(GA(a2.y), GA(a2.z)), GA(a2.w));
                u64 b4 = mul2(mul2(GA(a3.x), GA(a3.y)), GA(a3.z));
                u64 b5 = mul2(mul2(GA(a3.w), GA(a4.x)), GA(a4.y));
                u64 b6 = mul2(mul2(GA(a4.z), GA(a4.w)), GA(a5.x));
                u64 b7 = mul2(mul2(GA(a5.y), GA(a5.z)), GA(a5.w));
                #undef GA
                float2 c0 = unpk(b0), c1 = unpk(b1), c2 = unpk(b2), c3 = unpk(b3);
                float2 c4 = unpk(b4), c5 = unpk(b5), c6 = unpk(b6), c7 = unpk(b7);
                float mxx = fmaxf(fmaxf(fmaxf(c0.x, c1.x), fmaxf(c2.x, c3.x)),
                                  fmaxf(fmaxf(c4.x, c5.x), fmaxf(c6.x, c7.x)));
                float mxy = fmaxf(fmaxf(fmaxf(c0.y, c1.y), fmaxf(c2.y, c3.y)),
                                  fmaxf(fmaxf(c4.y, c5.y), fmaxf(c6.y, c7.y)));
                u64 mneg = pk(-mxx * kexp, -mxy * kexp);
                float sx = 0.0f, sy = 0.0f;
                #pragma unroll
                {
                    u64 t0 = fma2(b0, kexp2, mneg); float2 f0 = unpk(t0); sx += ex2(f0.x); sy += ex2(f0.y);
                    u64 t1 = fma2(b1, kexp2, mneg); float2 f1 = unpk(t1); sx += ex2(f1.x); sy += ex2(f1.y);
                    u64 t2 = fma2(b2, kexp2, mneg); float2 f2 = unpk(t2); sx += ex2(f2.x); sy += ex2(f2.y);
                    u64 t3 = fma2(b3, kexp2, mneg); float2 f3 = unpk(t3); sx += ex2(f3.x); sy += ex2(f3.y);
                    u64 t4 = fma2(b4, kexp2, mneg); float2 f4 = unpk(t4); sx += ex2(f4.x); sy += ex2(f4.y);
                    u64 t5 = fma2(b5, kexp2, mneg); float2 f5 = unpk(t5); sx += ex2(f5.x); sy += ex2(f5.y);
                    u64 t6 = fma2(b6, kexp2, mneg); float2 f6 = unpk(t6); sx += ex2(f6.x); sy += ex2(f6.y);
                    u64 t7 = fma2(b7, kexp2, mneg); float2 f7 = unpk(t7); sx += ex2(f7.x); sy += ex2(f7.y);
                }
                float cvx = fmaf(lg2(sx), KLOG, mxx * s3);
                float cvy = fmaf(lg2(sy), KLOG, mxy * s3);
                g_Cv2[item * 16 + j] = pk(cvx, cvy);
                lmax = fmaxf(lmax, fmaxf(cvx, cvy));
            }
            block_max_atomic(lmax, slotCv);
        }
        grid_sync();

        // ---- Phase B: matvec + LSE_m; hs kept in registers across barrier ----
        float hsx = 0.0f, hsy = 0.0f;
        const int g = 2 * wid + hf;               // valid when wid < NG/2
        {
            float s1 = get_scale(slotCv);
            float lmax = 0.0f;
            if (wid < NG / 2) {
                u64 h[NM];
                #pragma unroll
                for (int m = 0; m < NM; m++) h[m] = 0ull;
                #pragma unroll
                for (int c = 0; c < NC; c++) {
                    u64 cvc = g_Cv2[(c * NG + g) * 16 + j];
                    #pragma unroll
                    for (int m = 0; m < NM; m++) h[m] = fma2(ws2[m * NC + c], cvc, h[m]);
                }
                float2 hh[NM];
                #pragma unroll
                for (int m = 0; m < NM; m++) hh[m] = unpk(h[m]);
                float mxx = hh[0].x, mxy = hh[0].y;
                #pragma unroll
                for (int m = 1; m < NM; m++) { mxx = fmaxf(mxx, hh[m].x); mxy = fmaxf(mxy, hh[m].y); }
                float k1 = s1 * KEXP;             // scale folded into LSE
                u64 k12 = pk(k1, k1), mneg = pk(-mxx * k1, -mxy * k1);
                float sx = 0.0f, sy = 0.0f;
                #pragma unroll
                for (int m = 0; m < NM; m++) {
                    u64 t = fma2(h[m], k12, mneg);
                    float2 f = unpk(t);
                    sx += ex2(f.x); sy += ex2(f.y);
                }
                hsx = fmaf(lg2(sx), KLOG, mxx * s1);
                hsy = fmaf(lg2(sy), KLOG, mxy * s1);
                lmax = fmaxf(hsx, hsy);
            }
            block_max_atomic(lmax, slotHs);
        }
        grid_sync();

        // ---- merge (fused former Phase C): same warps, hs from registers ----
        {
            float sR = get_scale(slotR);
            float s2 = get_scale(slotHs);
            float lmax = 0.0f;
            if (wid < NG / 2) {
                float2 rr = unpk(g_Rt2[g * 16 + j]);
                float ax = rr.x * sR, ay = rr.y * sR;
                float bx = hsx * s2,  by = hsy * s2;
                float mxx = fmaxf(ax, bx), mnx = fminf(ax, bx);
                float mxy = fmaxf(ay, by), mny = fminf(ay, by);
                float rx = fmaf(lg2(1.0f + ex2((mnx - mxx) * KEXP)), KLOG, mxx);
                float ry = fmaf(lg2(1.0f + ex2((mny - mxy) * KEXP)), KLOG, mxy);
                g_Rt2[g * 16 + j] = pk(rx, ry);
                lmax = fmaxf(rx, ry);
            }
            block_max_atomic(lmax, slotRn);
        }
        grid_sync();

        slotR = slotRn;
    }

    // ---- output: scale + unpack back to (B, G) ----
    if (gtid < NG * 32) {                         // gtid = b*NG + g
        float s = get_scale(slotR);
        int b = gtid >> 11, g = gtid & (NG - 1);
        float2 v = unpk(g_Rt2[g * 16 + (b >> 1)]);
        out[gtid] = ((b & 1) ? v.y : v.x) * s;
    }
}

// ---------------------------------------------------------------------------
extern "C" void kernel_launch(void* const* d_in, const int* in_sizes, int n_in,
                              void* d_out, int out_size) {
    const float* x = (const float*)d_in[0];   // (32, 2048) f32
    const float* W = (const float*)d_in[1];   // (16, 16) f32
    const int*   I = (const int*)  d_in[2];   // (16, 2048, 8, 3) i32
    float* out = (float*)d_out;               // (32, 2048) f32

    k_persist<<<NBLK, NTHR>>>(x, W, I, out);
}